// round 2
// baseline (speedup 1.0000x reference)
#include <cuda_runtime.h>
#include <math.h>

// Problem constants
#define T_TOK 8192   // B*S
#define DD    128
#define MM    64

typedef unsigned long long ull;

// ---------------- scratch (__device__ globals: no allocation allowed) -------
__device__ float g_cbuf[T_TOK * MM];   // c[t][m] = timing*gate*score
__device__ float g_uT[DD * MM];        // u transposed [d][m]
__device__ float g_WgT[DD * MM];       // Wg transposed [d][m]
__device__ float g_bveff[MM];
__device__ float g_bc[MM * DD];        // bt + char

// ---------------- f32x2 packed helpers --------------------------------------
__device__ __forceinline__ ull pack2(float a, float b) {
    ull r;
    asm("mov.b64 %0, {%1, %2};" : "=l"(r) : "r"(__float_as_uint(a)), "r"(__float_as_uint(b)));
    return r;
}
__device__ __forceinline__ ull fma2(ull a, ull b, ull c) {
    ull d;
    asm("fma.rn.f32x2 %0, %1, %2, %3;" : "=l"(d) : "l"(a), "l"(b), "l"(c));
    return d;
}
__device__ __forceinline__ ull add2(ull a, ull b) {
    ull d;
    asm("add.rn.f32x2 %0, %1, %2;" : "=l"(d) : "l"(a), "l"(b));
    return d;
}
__device__ __forceinline__ float2 unpack2(ull v) {
    float2 r;
    asm("mov.b64 {%0, %1}, %2;" : "=f"(r.x), "=f"(r.y) : "l"(v));
    return r;
}

// ---------------- Kernel A: tiny precompute ---------------------------------
// u[m,d] = sum_e Wt[m,d,e]*Wv[m,e];  bveff[m] = bv[m] + sum_e (bt+char)[m,e]*Wv[m,e]
// bc[m,e] = bt[m,e]+char[m,e];  WgT[d][m] = Wg[m][d]
__global__ void __launch_bounds__(128) ka_precompute(
    const float* __restrict__ Wt, const float* __restrict__ bt,
    const float* __restrict__ chr, const float* __restrict__ Wg,
    const float* __restrict__ Wv, const float* __restrict__ bv)
{
    int m = blockIdx.x;
    int tid = threadIdx.x;          // tid indexes e (or d)
    __shared__ float wv_s[128];
    __shared__ float red[4];

    float wv = Wv[m * DD + tid];
    wv_s[tid] = wv;
    float bcv = bt[m * DD + tid] + chr[m * DD + tid];
    g_bc[m * DD + tid] = bcv;
    g_WgT[tid * MM + m] = Wg[m * DD + tid];
    __syncthreads();

    int lane = tid & 31, warp = tid >> 5;
    // bveff
    {
        float v = bcv * wv;
        #pragma unroll
        for (int o = 16; o > 0; o >>= 1) v += __shfl_down_sync(0xffffffffu, v, o);
        if (lane == 0) red[warp] = v;
        __syncthreads();
        if (tid == 0) g_bveff[m] = bv[m] + red[0] + red[1] + red[2] + red[3];
        __syncthreads();
    }
    // u rows
    for (int d = 0; d < DD; ++d) {
        float v = Wt[((size_t)m * DD + d) * DD + tid] * wv_s[tid];
        #pragma unroll
        for (int o = 16; o > 0; o >>= 1) v += __shfl_down_sync(0xffffffffu, v, o);
        if (lane == 0) red[warp] = v;
        __syncthreads();
        if (tid == 0) g_uT[d * MM + m] = red[0] + red[1] + red[2] + red[3];
        __syncthreads();
    }
}

// ---------------- Kernel B: selector / scores / c / victory_potential -------
// 16 tokens per block, 256 threads.
__global__ void __launch_bounds__(256) kb_selector(
    const float* __restrict__ x, const float* __restrict__ ctx,
    const float* __restrict__ W1, const float* __restrict__ b1,
    const float* __restrict__ W2, const float* __restrict__ b2,
    const float* __restrict__ O,  const float* __restrict__ bg,
    float* __restrict__ out)
{
    __shared__ float sin_s[16][256];   // [tok][concat dim]; first 128 = x
    __shared__ float hs[16][256];
    __shared__ float ls[16][64];
    __shared__ float vs[16][64];

    int t0 = blockIdx.x * 16;
    int tid = threadIdx.x;

    // load concat(x, context)
    #pragma unroll
    for (int k = 0; k < 16; ++k) {
        int idx = tid + k * 256;
        int tok = idx >> 8, col = idx & 255;
        float v = (col < 128) ? x[(size_t)(t0 + tok) * DD + col]
                              : ctx[(size_t)(t0 + tok) * DD + (col - 128)];
        sin_s[tok][col] = v;
    }
    __syncthreads();

    // h = gelu(sel_in @ W1 + b1); thread owns column j for all 16 tokens
    {
        int j = tid;
        float acc[16];
        float bj = b1[j];
        #pragma unroll
        for (int q = 0; q < 16; ++q) acc[q] = bj;
        for (int i = 0; i < 256; ++i) {
            float w = W1[i * 256 + j];
            #pragma unroll
            for (int q = 0; q < 16; ++q) acc[q] = fmaf(sin_s[q][i], w, acc[q]);
        }
        #pragma unroll
        for (int q = 0; q < 16; ++q) {
            float v = acc[q];
            hs[q][j] = 0.5f * v * (1.0f + erff(v * 0.70710678118654752f));
        }
    }
    __syncthreads();

    int n  = tid & 63;
    int tq = tid >> 6;      // 4 token groups
    int tb = tq * 4;

    // logits = h @ W2 + b2
    {
        float acc[4];
        float bn = b2[n];
        #pragma unroll
        for (int q = 0; q < 4; ++q) acc[q] = bn;
        for (int j = 0; j < 256; ++j) {
            float w = W2[j * 64 + n];
            #pragma unroll
            for (int q = 0; q < 4; ++q) acc[q] = fmaf(hs[tb + q][j], w, acc[q]);
        }
        #pragma unroll
        for (int q = 0; q < 4; ++q) ls[tb + q][n] = acc[q];
    }
    __syncthreads();

    // softmax per token (thread per token)
    if (tid < 16) {
        float mx = -1e30f;
        #pragma unroll
        for (int k = 0; k < 64; ++k) mx = fmaxf(mx, ls[tid][k]);
        float s = 0.f;
        #pragma unroll
        for (int k = 0; k < 64; ++k) { float e = expf(ls[tid][k] - mx); ls[tid][k] = e; s += e; }
        float inv = 1.0f / s;
        #pragma unroll
        for (int k = 0; k < 64; ++k) ls[tid][k] *= inv;
    }
    __syncthreads();

    // timing / victory / gates / c ; thread owns mechanism n for 4 tokens
    {
        float ta[4], va[4], gl[4];
        float tb0 = bg[n], vb0 = g_bveff[n];
        #pragma unroll
        for (int q = 0; q < 4; ++q) { ta[q] = tb0; va[q] = vb0; gl[q] = 0.f; }
        for (int d = 0; d < DD; ++d) {
            float wg = g_WgT[d * MM + n];
            float wu = g_uT[d * MM + n];
            #pragma unroll
            for (int q = 0; q < 4; ++q) {
                float xv = sin_s[tb + q][d];
                ta[q] = fmaf(xv, wg, ta[q]);
                va[q] = fmaf(xv, wu, va[q]);
            }
        }
        for (int mm = 0; mm < MM; ++mm) {
            float o = O[mm * MM + n];
            #pragma unroll
            for (int q = 0; q < 4; ++q) gl[q] = fmaf(ls[tb + q][mm], o, gl[q]);
        }
        #pragma unroll
        for (int q = 0; q < 4; ++q) {
            float sc     = ls[tb + q][n];
            float timing = 1.0f / (1.0f + expf(-ta[q]));
            float vic    = 1.0f / (1.0f + expf(-va[q]));
            float gate   = 1.0f + tanhf(gl[q]);
            g_cbuf[(size_t)(t0 + tb + q) * MM + n] = timing * gate * sc;
            vs[tb + q][n] = vic * sc;
        }
    }
    __syncthreads();

    // victory_potential
    if (tid < 16) {
        float s = 0.f;
        #pragma unroll
        for (int k = 0; k < 64; ++k) s += vs[tid][k];
        out[(size_t)T_TOK * DD + t0 + tid] = s;
    }
}

// ---------------- Kernel C: main fused GEMM + integrate ---------------------
// Block tile: 32 tokens x 128 e cols. 128 threads:
//   eg = tid&31 -> e0 = eg*4 (4 e cols);  tg = tid>>5 -> 8 tokens (4 f32x2 pairs)
#define PADC 34
__global__ void __launch_bounds__(128, 2) kc_main(
    const float* __restrict__ x, const float* __restrict__ Wt,
    const float* __restrict__ Wi, const float* __restrict__ bi,
    float* __restrict__ out)
{
    __shared__ float xs[128][PADC];    // x transposed [d][tok]
    __shared__ float cs[128][PADC];    // rows 0..63: c[m][tok]; phase2: sel[e][tok]

    int t0  = blockIdx.x * 32;
    int tid = threadIdx.x;

    // load x transposed
    #pragma unroll
    for (int k = 0; k < 32; ++k) {
        int idx = tid + k * 128;
        int tok = idx >> 7, d = idx & 127;
        xs[d][tok] = x[(size_t)(t0 + tok) * DD + d];
    }
    // load c (coalesced over m), store transposed
    #pragma unroll
    for (int k = 0; k < 16; ++k) {
        int idx = tid + k * 128;
        int tok = idx >> 6, m = idx & 63;
        cs[m][tok] = g_cbuf[(size_t)(t0 + tok) * MM + m];
    }
    __syncthreads();

    int eg = tid & 31, tg = tid >> 5;
    int e0 = eg * 4, tb = tg * 8;

    ull acc[4][4];
    #pragma unroll
    for (int i = 0; i < 4; ++i)
        #pragma unroll
        for (int p = 0; p < 4; ++p) acc[i][p] = 0ULL;

    for (int m = 0; m < MM; ++m) {
        ull y[4][4];
        #pragma unroll
        for (int i = 0; i < 4; ++i)
            #pragma unroll
            for (int p = 0; p < 4; ++p) y[i][p] = 0ULL;

        const float4* WtB = ((const float4*)Wt) + (size_t)m * 4096 + eg;
        #pragma unroll 4
        for (int d = 0; d < 128; ++d) {
            float4 w = WtB[d * 32];
            ull wq[4];
            wq[0] = pack2(w.x, w.x); wq[1] = pack2(w.y, w.y);
            wq[2] = pack2(w.z, w.z); wq[3] = pack2(w.w, w.w);
            ull xp[4];
            #pragma unroll
            for (int p = 0; p < 4; ++p)
                xp[p] = *(const ull*)&xs[d][tb + 2 * p];
            #pragma unroll
            for (int i = 0; i < 4; ++i)
                #pragma unroll
                for (int p = 0; p < 4; ++p)
                    y[i][p] = fma2(xp[p], wq[i], y[i][p]);
        }
        // acc += c[tok][m] * (y + bc[m])
        float4 b4 = ((const float4*)g_bc)[m * 32 + eg];
        ull bb[4];
        bb[0] = pack2(b4.x, b4.x); bb[1] = pack2(b4.y, b4.y);
        bb[2] = pack2(b4.z, b4.z); bb[3] = pack2(b4.w, b4.w);
        ull cp[4];
        #pragma unroll
        for (int p = 0; p < 4; ++p)
            cp[p] = *(const ull*)&cs[m][tb + 2 * p];
        #pragma unroll
        for (int i = 0; i < 4; ++i)
            #pragma unroll
            for (int p = 0; p < 4; ++p)
                acc[i][p] = fma2(add2(y[i][p], bb[i]), cp[p], acc[i][p]);
    }

    __syncthreads();   // everyone done reading cs (c tile)
    // stash selected into cs as sel[e][tok]
    #pragma unroll
    for (int i = 0; i < 4; ++i)
        #pragma unroll
        for (int p = 0; p < 4; ++p)
            *(ull*)&cs[e0 + i][tb + 2 * p] = acc[i][p];
    __syncthreads();

    // integrated = concat(x, selected) @ Wi + bi
    ull o[4][4];
    #pragma unroll
    for (int i = 0; i < 4; ++i)
        #pragma unroll
        for (int p = 0; p < 4; ++p) o[i][p] = 0ULL;

    #pragma unroll 4
    for (int k = 0; k < 128; ++k) {
        float4 w = ((const float4*)Wi)[k * 32 + eg];
        ull wq[4];
        wq[0] = pack2(w.x, w.x); wq[1] = pack2(w.y, w.y);
        wq[2] = pack2(w.z, w.z); wq[3] = pack2(w.w, w.w);
        ull ap[4];
        #pragma unroll
        for (int p = 0; p < 4; ++p) ap[p] = *(const ull*)&xs[k][tb + 2 * p];
        #pragma unroll
        for (int i = 0; i < 4; ++i)
            #pragma unroll
            for (int p = 0; p < 4; ++p)
                o[i][p] = fma2(ap[p], wq[i], o[i][p]);
    }
    #pragma unroll 4
    for (int k = 0; k < 128; ++k) {
        float4 w = ((const float4*)Wi)[(k + 128) * 32 + eg];
        ull wq[4];
        wq[0] = pack2(w.x, w.x); wq[1] = pack2(w.y, w.y);
        wq[2] = pack2(w.z, w.z); wq[3] = pack2(w.w, w.w);
        ull ap[4];
        #pragma unroll
        for (int p = 0; p < 4; ++p) ap[p] = *(const ull*)&cs[k][tb + 2 * p];
        #pragma unroll
        for (int i = 0; i < 4; ++i)
            #pragma unroll
            for (int p = 0; p < 4; ++p)
                o[i][p] = fma2(ap[p], wq[i], o[i][p]);
    }

    float4 bv4 = ((const float4*)bi)[eg];
    #pragma unroll
    for (int p = 0; p < 4; ++p) {
        float2 v0 = unpack2(o[0][p]);
        float2 v1 = unpack2(o[1][p]);
        float2 v2 = unpack2(o[2][p]);
        float2 v3 = unpack2(o[3][p]);
        float4 r0 = make_float4(v0.x + bv4.x, v1.x + bv4.y, v2.x + bv4.z, v3.x + bv4.w);
        float4 r1 = make_float4(v0.y + bv4.x, v1.y + bv4.y, v2.y + bv4.z, v3.y + bv4.w);
        *(float4*)&out[(size_t)(t0 + tb + 2 * p) * DD + e0]     = r0;
        *(float4*)&out[(size_t)(t0 + tb + 2 * p + 1) * DD + e0] = r1;
    }
}

// ---------------- launch -----------------------------------------------------
extern "C" void kernel_launch(void* const* d_in, const int* in_sizes, int n_in,
                              void* d_out, int out_size)
{
    const float* x    = (const float*)d_in[0];
    const float* ctx  = (const float*)d_in[1];
    const float* Wt   = (const float*)d_in[2];
    const float* bt   = (const float*)d_in[3];
    const float* chr  = (const float*)d_in[4];
    const float* Wg   = (const float*)d_in[5];
    const float* bg   = (const float*)d_in[6];
    const float* Wv   = (const float*)d_in[7];
    const float* bv   = (const float*)d_in[8];
    const float* O    = (const float*)d_in[9];
    const float* W1   = (const float*)d_in[10];
    const float* b1   = (const float*)d_in[11];
    const float* W2   = (const float*)d_in[12];
    const float* b2   = (const float*)d_in[13];
    const float* Wi   = (const float*)d_in[14];
    const float* bi   = (const float*)d_in[15];
    float* out = (float*)d_out;

    ka_precompute<<<64, 128>>>(Wt, bt, chr, Wg, Wv, bv);
    kb_selector<<<T_TOK / 16, 256>>>(x, ctx, W1, b1, W2, b2, O, bg, out);
    kc_main<<<T_TOK / 32, 128>>>(x, Wt, Wi, bi, out);
}